// round 7
// baseline (speedup 1.0000x reference)
#include <cuda_runtime.h>
#include <math.h>
#include <stdint.h>

#define N_NODES 100000
#define N_EDGES 1600000
#define N_GRAPHS 256
#define D_HID 64
#define SCAN_BLOCKS 98   // ceil(100000/1024)

// ---------------- scratch (device globals; no allocation allowed) ----------------
__device__ __align__(16) float g_h[(size_t)N_NODES * D_HID];    // gemm output ("h" per layer)
__device__ __align__(16) float g_out[(size_t)N_NODES * D_HID];  // aggregated output per layer
__device__ float g_als[N_NODES];
__device__ float g_ald[N_NODES];
__device__ int   g_cnt[N_NODES];                  // histogram / scatter cursor
__device__ int   g_rowptr[N_NODES + 1];
__device__ int   g_col[N_EDGES];                  // src node per CSR slot
__device__ int   g_bsum[128];
__device__ float g_pool[N_GRAPHS * D_HID];
__device__ int   g_pcnt[N_GRAPHS];
__device__ int   g_shift;                         // 0: indices are int32, 1: int64

// ---------------- index dtype detection ----------------
// int64 values here are < 2^31 and non-negative, so their high 32-bit words are 0.
// For int32 data the odd positions hold real random node ids (all-zero prob ~0).
__global__ void detect_kernel(const int* __restrict__ ei32) {
    int nz = 0;
#pragma unroll
    for (int k = 0; k < 16; k++) nz |= ei32[2 * k + 1];
    g_shift = (nz == 0) ? 1 : 0;
}

__device__ __forceinline__ int load_src(const int* p, int e, int sh) {
    return p[(size_t)e << sh];
}
__device__ __forceinline__ int load_dst(const int* p, int e, int sh) {
    return p[((size_t)N_EDGES + e) << sh];
}

// ---------------- zeroing ----------------
__global__ void zero_all_kernel() {
    int i = blockIdx.x * blockDim.x + threadIdx.x;
    if (i < N_NODES) g_cnt[i] = 0;
    if (i < N_GRAPHS * D_HID) g_pool[i] = 0.f;
    if (i < N_GRAPHS) g_pcnt[i] = 0;
}
__global__ void zero_cnt_kernel() {
    int i = blockIdx.x * blockDim.x + threadIdx.x;
    if (i < N_NODES) g_cnt[i] = 0;
}

// ---------------- CSR build ----------------
__global__ void count_kernel(const int* __restrict__ ei) {
    int e = blockIdx.x * blockDim.x + threadIdx.x;
    int sh = g_shift;
    if (e < N_EDGES) atomicAdd(&g_cnt[load_dst(ei, e, sh)], 1);
}

__global__ void scan1_kernel() {
    __shared__ int sh[1024];
    int i = blockIdx.x * 1024 + threadIdx.x;
    int v = (i < N_NODES) ? g_cnt[i] : 0;
    sh[threadIdx.x] = v;
    __syncthreads();
#pragma unroll
    for (int off = 1; off < 1024; off <<= 1) {
        int t = (threadIdx.x >= off) ? sh[threadIdx.x - off] : 0;
        __syncthreads();
        sh[threadIdx.x] += t;
        __syncthreads();
    }
    if (i < N_NODES) g_rowptr[i] = sh[threadIdx.x] - v;   // exclusive
    if (threadIdx.x == 1023) g_bsum[blockIdx.x] = sh[1023];
}

__global__ void scan2_kernel(int nb) {
    __shared__ int sh[128];
    int t = threadIdx.x;
    int v = (t < nb) ? g_bsum[t] : 0;
    sh[t] = v;
    __syncthreads();
#pragma unroll
    for (int off = 1; off < 128; off <<= 1) {
        int tv = (t >= off) ? sh[t - off] : 0;
        __syncthreads();
        sh[t] += tv;
        __syncthreads();
    }
    if (t < nb) g_bsum[t] = sh[t] - v;                    // exclusive over block sums
    if (t == 0) g_rowptr[N_NODES] = N_EDGES;
}

__global__ void scan3_kernel() {
    int i = blockIdx.x * 1024 + threadIdx.x;
    if (i < N_NODES) g_rowptr[i] += g_bsum[blockIdx.x];
}

__global__ void scatter_kernel(const int* __restrict__ ei) {
    int e = blockIdx.x * blockDim.x + threadIdx.x;
    int sh = g_shift;
    if (e < N_EDGES) {
        int d = load_dst(ei, e, sh);
        int pos = g_rowptr[d] + atomicAdd(&g_cnt[d], 1);
        g_col[pos] = load_src(ei, e, sh);
    }
}

// ---------------- fused GEMM + attention-logit reduction ----------------
// h = X @ W  (K x 64), als = h . a_src, ald = h . a_dst
// 256 threads/block = 16 nodes x 16 threads; each thread computes 4 output cols.
// USE_GOUT: read input rows from the device global g_out (layer 2) instead of X.
template <int K, bool USE_GOUT>
__global__ void __launch_bounds__(256) gemm_att_kernel(
    const float* __restrict__ X, const float* __restrict__ W,
    const float* __restrict__ avs, const float* __restrict__ avd)
{
    __shared__ __align__(16) float Ws[K * 64];
    __shared__ float Xs[16 * K];
    __shared__ float As[64], Ad[64];

    int tid = threadIdx.x;
    for (int idx = tid; idx < K * 64; idx += 256) Ws[idx] = W[idx];
    if (tid < 64) { As[tid] = avs[tid]; Ad[tid] = avd[tid]; }
    int nb = blockIdx.x * 16;
    const float* src_ptr = USE_GOUT ? g_out : X;
    for (int idx = tid; idx < 16 * K; idx += 256) {
        int nl = idx / K, k = idx - nl * K;
        int node = nb + nl;
        Xs[idx] = (node < N_NODES) ? src_ptr[(size_t)node * K + k] : 0.f;
    }
    __syncthreads();

    int nl = tid >> 4;
    int l16 = tid & 15;
    int node = nb + nl;
    float a0 = 0.f, a1 = 0.f, a2 = 0.f, a3 = 0.f;
    const float4* W4 = reinterpret_cast<const float4*>(Ws);
    const float* xr = &Xs[nl * K];
#pragma unroll
    for (int k = 0; k < K; k++) {
        float xv = xr[k];
        float4 w = W4[k * 16 + l16];
        a0 = fmaf(xv, w.x, a0);
        a1 = fmaf(xv, w.y, a1);
        a2 = fmaf(xv, w.z, a2);
        a3 = fmaf(xv, w.w, a3);
    }
    int c0 = l16 * 4;
    float ps = a0 * As[c0] + a1 * As[c0 + 1] + a2 * As[c0 + 2] + a3 * As[c0 + 3];
    float pd = a0 * Ad[c0] + a1 * Ad[c0 + 1] + a2 * Ad[c0 + 2] + a3 * Ad[c0 + 3];
#pragma unroll
    for (int off = 8; off; off >>= 1) {
        ps += __shfl_xor_sync(0xffffffffu, ps, off, 16);
        pd += __shfl_xor_sync(0xffffffffu, pd, off, 16);
    }
    if (node < N_NODES) {
        *reinterpret_cast<float4*>(&g_h[(size_t)node * 64 + c0]) = make_float4(a0, a1, a2, a3);
        if (l16 == 0) { g_als[node] = ps; g_ald[node] = pd; }
    }
}

// ---------------- fused online-softmax aggregation (one warp per dst node) ----------------
__global__ void __launch_bounds__(256) agg_kernel(const float* __restrict__ bias, int act) {
    int i = (blockIdx.x * blockDim.x + threadIdx.x) >> 5;
    int lane = threadIdx.x & 31;
    if (i >= N_NODES) return;

    float ald_i = g_ald[i];
    // self-loop (PyG GATConv adds them)
    float e0 = g_als[i] + ald_i;
    e0 = (e0 >= 0.f) ? e0 : 0.2f * e0;
    float m = e0, s = 1.f;
    float2 hv = *reinterpret_cast<const float2*>(&g_h[(size_t)i * 64 + 2 * lane]);
    float a0 = hv.x, a1 = hv.y;

    int beg = g_rowptr[i], end = g_rowptr[i + 1];
    for (int j0 = beg; j0 < end; j0 += 32) {
        int cnt = end - j0;
        if (cnt > 32) cnt = 32;
        int src = 0;
        float e = -3.0e38f;
        if (lane < cnt) {
            src = g_col[j0 + lane];
            e = g_als[src] + ald_i;
            e = (e >= 0.f) ? e : 0.2f * e;
        }
        // chunk max
        float cm = e;
#pragma unroll
        for (int off = 16; off; off >>= 1)
            cm = fmaxf(cm, __shfl_xor_sync(0xffffffffu, cm, off));
        if (cm > m) {
            float r = __expf(m - cm);
            s *= r; a0 *= r; a1 *= r;
            m = cm;
        }
        float w = (lane < cnt) ? __expf(e - m) : 0.f;
        float ws = w;
#pragma unroll
        for (int off = 16; off; off >>= 1)
            ws += __shfl_xor_sync(0xffffffffu, ws, off);
        s += ws;
        for (int jj = 0; jj < cnt; ++jj) {
            float wj = __shfl_sync(0xffffffffu, w, jj);
            int sj = __shfl_sync(0xffffffffu, src, jj);
            float2 hs = *reinterpret_cast<const float2*>(&g_h[(size_t)sj * 64 + 2 * lane]);
            a0 = fmaf(wj, hs.x, a0);
            a1 = fmaf(wj, hs.y, a1);
        }
    }
    float inv = 1.f / (s + 1e-16f);
    float o0 = a0 * inv + bias[2 * lane];
    float o1 = a1 * inv + bias[2 * lane + 1];
    if (act) {
        o0 = (o0 >= 0.f) ? o0 : 0.01f * o0;
        o1 = (o1 >= 0.f) ? o1 : 0.01f * o1;
    }
    *reinterpret_cast<float2*>(&g_out[(size_t)i * 64 + 2 * lane]) = make_float2(o0, o1);
}

// ---------------- pooling (batch is sorted -> segment-flush accumulation) ----------------
__global__ void __launch_bounds__(64) pool_kernel(const int* __restrict__ batch) {
    const int CH = 512;
    __shared__ int bsh[CH];
    int start = blockIdx.x * CH;
    int end = start + CH;
    if (end > N_NODES) end = N_NODES;
    int c = threadIdx.x;  // 0..63
    int sh = g_shift;
    for (int idx = c; idx < end - start; idx += 64)
        bsh[idx] = batch[(size_t)(start + idx) << sh];
    __syncthreads();
    if (start >= end) return;
    int cur = bsh[0];
    float acc = 0.f;
    int cnt = 0;
    for (int n = start; n < end; n++) {
        int b = bsh[n - start];
        if (b != cur) {
            atomicAdd(&g_pool[cur * 64 + c], acc);
            if (c == 0) atomicAdd(&g_pcnt[cur], cnt);
            acc = 0.f; cnt = 0; cur = b;
        }
        acc += g_out[(size_t)n * 64 + c];
        cnt++;
    }
    atomicAdd(&g_pool[cur * 64 + c], acc);
    if (c == 0) atomicAdd(&g_pcnt[cur], cnt);
}

// ---------------- final FC ----------------
__global__ void fc_kernel(const float* __restrict__ fcW, const float* __restrict__ fcb,
                          float* __restrict__ out) {
    int g = threadIdx.x;  // 256 graphs
    float cnt = fmaxf((float)g_pcnt[g], 1.f);
    float inv = 1.f / cnt;
    float o0 = fcb[0], o1 = fcb[1];
#pragma unroll
    for (int c = 0; c < 64; c++) {
        float p = g_pool[g * 64 + c] * inv;
        o0 = fmaf(p, fcW[2 * c], o0);
        o1 = fmaf(p, fcW[2 * c + 1], o1);
    }
    out[2 * g] = o0;
    out[2 * g + 1] = o1;
}

// ---------------- launch ----------------
extern "C" void kernel_launch(void* const* d_in, const int* in_sizes, int n_in,
                              void* d_out, int out_size) {
    const float* x      = (const float*)d_in[0];
    const int*   ei     = (const int*)d_in[1];    // int32 or int64 (detected on device)
    const int*   batch  = (const int*)d_in[2];
    const float* W1     = (const float*)d_in[3];
    const float* asrc1  = (const float*)d_in[4];
    const float* adst1  = (const float*)d_in[5];
    const float* b1     = (const float*)d_in[6];
    const float* W2     = (const float*)d_in[7];
    const float* asrc2  = (const float*)d_in[8];
    const float* adst2  = (const float*)d_in[9];
    const float* b2     = (const float*)d_in[10];
    const float* fcW    = (const float*)d_in[11];
    const float* fcb    = (const float*)d_in[12];
    float* out = (float*)d_out;

    // index dtype detection + CSR build (same graph used by both layers)
    detect_kernel<<<1, 1>>>(ei);
    zero_all_kernel<<<(N_NODES + 255) / 256, 256>>>();
    count_kernel<<<(N_EDGES + 255) / 256, 256>>>(ei);
    scan1_kernel<<<SCAN_BLOCKS, 1024>>>();
    scan2_kernel<<<1, 128>>>(SCAN_BLOCKS);
    scan3_kernel<<<SCAN_BLOCKS, 1024>>>();
    zero_cnt_kernel<<<(N_NODES + 255) / 256, 256>>>();
    scatter_kernel<<<(N_EDGES + 255) / 256, 256>>>(ei);

    // layer 1
    gemm_att_kernel<72, false><<<(N_NODES + 15) / 16, 256>>>(x, W1, asrc1, adst1);
    agg_kernel<<<(N_NODES * 32 + 255) / 256, 256>>>(b1, 1);

    // layer 2 (input = g_out from layer 1, referenced directly in device code)
    gemm_att_kernel<64, true><<<(N_NODES + 15) / 16, 256>>>(nullptr, W2, asrc2, adst2);
    agg_kernel<<<(N_NODES * 32 + 255) / 256, 256>>>(b2, 0);

    // pool + fc
    pool_kernel<<<(N_NODES + 511) / 512, 64>>>(batch);
    fc_kernel<<<1, 256>>>(fcW, fcb, out);
}

// round 8
// speedup vs baseline: 1.2028x; 1.2028x over previous
#include <cuda_runtime.h>
#include <math.h>
#include <stdint.h>

#define N_NODES 100000
#define N_EDGES 1600000
#define N_GRAPHS 256
#define D_HID 64
#define SCAN_BLOCKS 98   // ceil(100000/1024)

// ---------------- scratch (device globals; no allocation allowed) ----------------
__device__ __align__(16) float g_h[(size_t)N_NODES * D_HID];    // gemm output ("h" per layer)
__device__ __align__(16) float g_out[(size_t)N_NODES * D_HID];  // aggregated output per layer
__device__ float g_als[N_NODES];
__device__ float g_ald[N_NODES];
__device__ int   g_cnt[N_NODES];                  // histogram / scatter cursor
__device__ int   g_rowptr[N_NODES + 1];
__device__ int   g_col[N_EDGES];                  // src node per CSR slot
__device__ int   g_bsum[128];
__device__ float g_pool[N_GRAPHS * D_HID];
__device__ int   g_pcnt[N_GRAPHS];
__device__ int   g_shift;                         // 0: indices are int32, 1: int64

__device__ __forceinline__ int load_src(const int* p, int e, int sh) {
    return p[(size_t)e << sh];
}
__device__ __forceinline__ int load_dst(const int* p, int e, int sh) {
    return p[((size_t)N_EDGES + e) << sh];
}

// ---------------- zero + index dtype detection (fused) ----------------
// int64 values here are < 2^31 and non-negative, so their high 32-bit words are 0.
// For int32 data the odd positions hold real random node ids (all-zero prob ~0).
__global__ void zero_all_kernel(const int* __restrict__ ei32) {
    int i = blockIdx.x * blockDim.x + threadIdx.x;
    if (i < N_NODES) g_cnt[i] = 0;
    if (i < N_GRAPHS * D_HID) g_pool[i] = 0.f;
    if (i < N_GRAPHS) g_pcnt[i] = 0;
    if (i == 0) {
        int nz = 0;
#pragma unroll
        for (int k = 0; k < 16; k++) nz |= ei32[2 * k + 1];
        g_shift = (nz == 0) ? 1 : 0;
    }
}

// ---------------- CSR build ----------------
__global__ void count_kernel(const int* __restrict__ ei) {
    int e = blockIdx.x * blockDim.x + threadIdx.x;
    int sh = g_shift;
    if (e < N_EDGES) atomicAdd(&g_cnt[load_dst(ei, e, sh)], 1);
}

__global__ void scan1_kernel() {
    __shared__ int sh[1024];
    int i = blockIdx.x * 1024 + threadIdx.x;
    int v = (i < N_NODES) ? g_cnt[i] : 0;
    sh[threadIdx.x] = v;
    __syncthreads();
#pragma unroll
    for (int off = 1; off < 1024; off <<= 1) {
        int t = (threadIdx.x >= off) ? sh[threadIdx.x - off] : 0;
        __syncthreads();
        sh[threadIdx.x] += t;
        __syncthreads();
    }
    if (i < N_NODES) g_rowptr[i] = sh[threadIdx.x] - v;   // exclusive
    if (threadIdx.x == 1023) g_bsum[blockIdx.x] = sh[1023];
}

__global__ void scan2_kernel(int nb) {
    __shared__ int sh[128];
    int t = threadIdx.x;
    int v = (t < nb) ? g_bsum[t] : 0;
    sh[t] = v;
    __syncthreads();
#pragma unroll
    for (int off = 1; off < 128; off <<= 1) {
        int tv = (t >= off) ? sh[t - off] : 0;
        __syncthreads();
        sh[t] += tv;
        __syncthreads();
    }
    if (t < nb) g_bsum[t] = sh[t] - v;                    // exclusive over block sums
    if (t == 0) g_rowptr[N_NODES] = N_EDGES;
}

// scan3 also re-zeros g_cnt (used as scatter cursor next) -> one fewer launch
__global__ void scan3_kernel() {
    int i = blockIdx.x * 1024 + threadIdx.x;
    if (i < N_NODES) {
        g_rowptr[i] += g_bsum[blockIdx.x];
        g_cnt[i] = 0;
    }
}

__global__ void scatter_kernel(const int* __restrict__ ei) {
    int e = blockIdx.x * blockDim.x + threadIdx.x;
    int sh = g_shift;
    if (e < N_EDGES) {
        int d = load_dst(ei, e, sh);
        int pos = g_rowptr[d] + atomicAdd(&g_cnt[d], 1);
        g_col[pos] = load_src(ei, e, sh);
    }
}

// ---------------- fused GEMM + attention-logit reduction ----------------
// h = X @ W  (K x 64), als = h . a_src, ald = h . a_dst
// NPB=32 nodes/block, 512 threads = 32 nodes x 16 threads; 4 output cols/thread.
// USE_GOUT: read input rows from the device global g_out (layer 2) instead of X.
#define NPB 32
template <int K, bool USE_GOUT>
__global__ void __launch_bounds__(NPB * 16) gemm_att_kernel(
    const float* __restrict__ X, const float* __restrict__ W,
    const float* __restrict__ avs, const float* __restrict__ avd)
{
    __shared__ __align__(16) float Ws[K * 64];
    __shared__ float Xs[NPB * K];
    __shared__ float As[64], Ad[64];

    int tid = threadIdx.x;
    for (int idx = tid; idx < K * 64; idx += NPB * 16) Ws[idx] = W[idx];
    if (tid < 64) { As[tid] = avs[tid]; Ad[tid] = avd[tid]; }
    int nb = blockIdx.x * NPB;
    const float* src_ptr = USE_GOUT ? g_out : X;
    // node rows are contiguous -> fully coalesced block copy
    {
        int lim = NPB * K;
        int base = nb * K;
        int maxe = N_NODES * K - base;
        for (int idx = tid; idx < lim; idx += NPB * 16)
            Xs[idx] = (idx < maxe) ? src_ptr[(size_t)base + idx] : 0.f;
    }
    __syncthreads();

    int nl = tid >> 4;
    int l16 = tid & 15;
    int node = nb + nl;
    float a0 = 0.f, a1 = 0.f, a2 = 0.f, a3 = 0.f;
    const float4* W4 = reinterpret_cast<const float4*>(Ws);
    const float* xr = &Xs[nl * K];
#pragma unroll
    for (int k = 0; k < K; k++) {
        float xv = xr[k];
        float4 w = W4[k * 16 + l16];
        a0 = fmaf(xv, w.x, a0);
        a1 = fmaf(xv, w.y, a1);
        a2 = fmaf(xv, w.z, a2);
        a3 = fmaf(xv, w.w, a3);
    }
    int c0 = l16 * 4;
    float ps = a0 * As[c0] + a1 * As[c0 + 1] + a2 * As[c0 + 2] + a3 * As[c0 + 3];
    float pd = a0 * Ad[c0] + a1 * Ad[c0 + 1] + a2 * Ad[c0 + 2] + a3 * Ad[c0 + 3];
#pragma unroll
    for (int off = 8; off; off >>= 1) {
        ps += __shfl_xor_sync(0xffffffffu, ps, off, 16);
        pd += __shfl_xor_sync(0xffffffffu, pd, off, 16);
    }
    if (node < N_NODES) {
        *reinterpret_cast<float4*>(&g_h[(size_t)node * 64 + c0]) = make_float4(a0, a1, a2, a3);
        if (l16 == 0) { g_als[node] = ps; g_ald[node] = pd; }
    }
}

// ---------------- fused online-softmax aggregation (one warp per dst node) ----------------
__global__ void __launch_bounds__(256) agg_kernel(const float* __restrict__ bias, int act) {
    int i = (blockIdx.x * blockDim.x + threadIdx.x) >> 5;
    int lane = threadIdx.x & 31;
    if (i >= N_NODES) return;

    const float* hrow = &g_h[2 * lane];   // lane-fixed column offset

    float ald_i = g_ald[i];
    // self-loop (PyG GATConv adds them)
    float e0 = g_als[i] + ald_i;
    e0 = (e0 >= 0.f) ? e0 : 0.2f * e0;
    float m = e0, s = 1.f;
    float2 hv = *reinterpret_cast<const float2*>(hrow + (size_t)i * 64);
    float a0 = hv.x, a1 = hv.y;

    int beg = g_rowptr[i], end = g_rowptr[i + 1];
    for (int j0 = beg; j0 < end; j0 += 32) {
        int cnt = end - j0;
        if (cnt > 32) cnt = 32;
        int src = 0;
        float e = -3.0e38f;
        if (lane < cnt) {
            src = g_col[j0 + lane];
            e = g_als[src] + ald_i;
            e = (e >= 0.f) ? e : 0.2f * e;
        }
        // chunk max
        float cm = e;
#pragma unroll
        for (int off = 16; off; off >>= 1)
            cm = fmaxf(cm, __shfl_xor_sync(0xffffffffu, cm, off));
        if (cm > m) {
            float r = __expf(m - cm);
            s *= r; a0 *= r; a1 *= r;
            m = cm;
        }
        float w = (lane < cnt) ? __expf(e - m) : 0.f;
        float ws = w;
#pragma unroll
        for (int off = 16; off; off >>= 1)
            ws += __shfl_xor_sync(0xffffffffu, ws, off);
        s += ws;

        // gather, 4-wide for MLP
        int jj = 0;
        for (; jj + 4 <= cnt; jj += 4) {
            float w0 = __shfl_sync(0xffffffffu, w, jj);
            float w1 = __shfl_sync(0xffffffffu, w, jj + 1);
            float w2 = __shfl_sync(0xffffffffu, w, jj + 2);
            float w3 = __shfl_sync(0xffffffffu, w, jj + 3);
            int s0 = __shfl_sync(0xffffffffu, src, jj);
            int s1 = __shfl_sync(0xffffffffu, src, jj + 1);
            int s2 = __shfl_sync(0xffffffffu, src, jj + 2);
            int s3 = __shfl_sync(0xffffffffu, src, jj + 3);
            float2 h0 = *reinterpret_cast<const float2*>(hrow + (size_t)s0 * 64);
            float2 h1 = *reinterpret_cast<const float2*>(hrow + (size_t)s1 * 64);
            float2 h2 = *reinterpret_cast<const float2*>(hrow + (size_t)s2 * 64);
            float2 h3 = *reinterpret_cast<const float2*>(hrow + (size_t)s3 * 64);
            a0 = fmaf(w0, h0.x, a0); a1 = fmaf(w0, h0.y, a1);
            a0 = fmaf(w1, h1.x, a0); a1 = fmaf(w1, h1.y, a1);
            a0 = fmaf(w2, h2.x, a0); a1 = fmaf(w2, h2.y, a1);
            a0 = fmaf(w3, h3.x, a0); a1 = fmaf(w3, h3.y, a1);
        }
        for (; jj < cnt; ++jj) {
            float wj = __shfl_sync(0xffffffffu, w, jj);
            int sj = __shfl_sync(0xffffffffu, src, jj);
            float2 hs = *reinterpret_cast<const float2*>(hrow + (size_t)sj * 64);
            a0 = fmaf(wj, hs.x, a0);
            a1 = fmaf(wj, hs.y, a1);
        }
    }
    float inv = 1.f / (s + 1e-16f);
    float o0 = a0 * inv + bias[2 * lane];
    float o1 = a1 * inv + bias[2 * lane + 1];
    if (act) {
        o0 = (o0 >= 0.f) ? o0 : 0.01f * o0;
        o1 = (o1 >= 0.f) ? o1 : 0.01f * o1;
    }
    *reinterpret_cast<float2*>(&g_out[(size_t)i * 64 + 2 * lane]) = make_float2(o0, o1);
}

// ---------------- pooling (batch is sorted -> segment-flush accumulation) ----------------
#define POOL_CH 256
__global__ void __launch_bounds__(64) pool_kernel(const int* __restrict__ batch) {
    __shared__ int bsh[POOL_CH];
    int start = blockIdx.x * POOL_CH;
    int end = start + POOL_CH;
    if (end > N_NODES) end = N_NODES;
    int c = threadIdx.x;  // 0..63
    int sh = g_shift;
    for (int idx = c; idx < end - start; idx += 64)
        bsh[idx] = batch[(size_t)(start + idx) << sh];
    __syncthreads();
    if (start >= end) return;
    int cur = bsh[0];
    float acc = 0.f;
    int cnt = 0;
    for (int n = start; n < end; n++) {
        int b = bsh[n - start];
        if (b != cur) {
            atomicAdd(&g_pool[cur * 64 + c], acc);
            if (c == 0) atomicAdd(&g_pcnt[cur], cnt);
            acc = 0.f; cnt = 0; cur = b;
        }
        acc += g_out[(size_t)n * 64 + c];
        cnt++;
    }
    atomicAdd(&g_pool[cur * 64 + c], acc);
    if (c == 0) atomicAdd(&g_pcnt[cur], cnt);
}

// ---------------- final FC ----------------
__global__ void fc_kernel(const float* __restrict__ fcW, const float* __restrict__ fcb,
                          float* __restrict__ out) {
    int g = threadIdx.x;  // 256 graphs
    float cnt = fmaxf((float)g_pcnt[g], 1.f);
    float inv = 1.f / cnt;
    float o0 = fcb[0], o1 = fcb[1];
#pragma unroll
    for (int c = 0; c < 64; c++) {
        float p = g_pool[g * 64 + c] * inv;
        o0 = fmaf(p, fcW[2 * c], o0);
        o1 = fmaf(p, fcW[2 * c + 1], o1);
    }
    out[2 * g] = o0;
    out[2 * g + 1] = o1;
}

// ---------------- launch ----------------
extern "C" void kernel_launch(void* const* d_in, const int* in_sizes, int n_in,
                              void* d_out, int out_size) {
    const float* x      = (const float*)d_in[0];
    const int*   ei     = (const int*)d_in[1];    // int32 or int64 (detected on device)
    const int*   batch  = (const int*)d_in[2];
    const float* W1     = (const float*)d_in[3];
    const float* asrc1  = (const float*)d_in[4];
    const float* adst1  = (const float*)d_in[5];
    const float* b1     = (const float*)d_in[6];
    const float* W2     = (const float*)d_in[7];
    const float* asrc2  = (const float*)d_in[8];
    const float* adst2  = (const float*)d_in[9];
    const float* b2     = (const float*)d_in[10];
    const float* fcW    = (const float*)d_in[11];
    const float* fcb    = (const float*)d_in[12];
    float* out = (float*)d_out;

    // zero + dtype detect + CSR build (same graph used by both layers)
    zero_all_kernel<<<(N_NODES + 255) / 256, 256>>>(ei);
    count_kernel<<<(N_EDGES + 255) / 256, 256>>>(ei);
    scan1_kernel<<<SCAN_BLOCKS, 1024>>>();
    scan2_kernel<<<1, 128>>>(SCAN_BLOCKS);
    scan3_kernel<<<SCAN_BLOCKS, 1024>>>();
    scatter_kernel<<<(N_EDGES + 255) / 256, 256>>>(ei);

    // layer 1
    gemm_att_kernel<72, false><<<(N_NODES + NPB - 1) / NPB, NPB * 16>>>(x, W1, asrc1, adst1);
    agg_kernel<<<(N_NODES * 32 + 255) / 256, 256>>>(b1, 1);

    // layer 2 (input = g_out from layer 1, referenced directly in device code)
    gemm_att_kernel<64, true><<<(N_NODES + NPB - 1) / NPB, NPB * 16>>>(nullptr, W2, asrc2, adst2);
    agg_kernel<<<(N_NODES * 32 + 255) / 256, 256>>>(b2, 0);

    // pool + fc
    pool_kernel<<<(N_NODES + POOL_CH - 1) / POOL_CH, 64>>>(batch);
    fc_kernel<<<1, 256>>>(fcW, fcb, out);
}

// round 9
// speedup vs baseline: 1.3238x; 1.1006x over previous
#include <cuda_runtime.h>
#include <cuda_fp16.h>
#include <math.h>
#include <stdint.h>

#define N_NODES 100000
#define N_EDGES 1600000
#define N_GRAPHS 256
#define D_HID 64
#define SCAN_BLOCKS 98   // ceil(100000/1024)

// ---------------- scratch (device globals; no allocation allowed) ----------------
__device__ __align__(16) __half2 g_hh[(size_t)N_NODES * 32];    // h rows in fp16 (64 cols = 32 half2)
__device__ __align__(16) float g_out[(size_t)N_NODES * D_HID];  // aggregated output per layer
__device__ float g_als[N_NODES];
__device__ float g_ald[N_NODES];
__device__ int   g_cnt[N_NODES];                  // histogram / scatter cursor
__device__ int   g_rowptr[N_NODES + 1];
__device__ int   g_col[N_EDGES];                  // src node per CSR slot
__device__ int   g_bsum[128];
__device__ float g_pool[N_GRAPHS * D_HID];
__device__ int   g_pcnt[N_GRAPHS];
__device__ int   g_shift;                         // 0: indices are int32, 1: int64

__device__ __forceinline__ int load_src(const int* p, int e, int sh) {
    return p[(size_t)e << sh];
}
__device__ __forceinline__ int load_dst(const int* p, int e, int sh) {
    return p[((size_t)N_EDGES + e) << sh];
}

// ---------------- zero + index dtype detection (fused) ----------------
__global__ void zero_all_kernel(const int* __restrict__ ei32) {
    int i = blockIdx.x * blockDim.x + threadIdx.x;
    if (i < N_NODES) g_cnt[i] = 0;
    if (i < N_GRAPHS * D_HID) g_pool[i] = 0.f;
    if (i < N_GRAPHS) g_pcnt[i] = 0;
    if (i == 0) {
        int nz = 0;
#pragma unroll
        for (int k = 0; k < 16; k++) nz |= ei32[2 * k + 1];
        g_shift = (nz == 0) ? 1 : 0;
    }
}

// ---------------- CSR build ----------------
__global__ void count_kernel(const int* __restrict__ ei) {
    int e = blockIdx.x * blockDim.x + threadIdx.x;
    int sh = g_shift;
    if (e < N_EDGES) atomicAdd(&g_cnt[load_dst(ei, e, sh)], 1);
}

__global__ void scan1_kernel() {
    __shared__ int sh[1024];
    int i = blockIdx.x * 1024 + threadIdx.x;
    int v = (i < N_NODES) ? g_cnt[i] : 0;
    sh[threadIdx.x] = v;
    __syncthreads();
#pragma unroll
    for (int off = 1; off < 1024; off <<= 1) {
        int t = (threadIdx.x >= off) ? sh[threadIdx.x - off] : 0;
        __syncthreads();
        sh[threadIdx.x] += t;
        __syncthreads();
    }
    if (i < N_NODES) g_rowptr[i] = sh[threadIdx.x] - v;   // exclusive
    if (threadIdx.x == 1023) g_bsum[blockIdx.x] = sh[1023];
}

__global__ void scan2_kernel(int nb) {
    __shared__ int sh[128];
    int t = threadIdx.x;
    int v = (t < nb) ? g_bsum[t] : 0;
    sh[t] = v;
    __syncthreads();
#pragma unroll
    for (int off = 1; off < 128; off <<= 1) {
        int tv = (t >= off) ? sh[t - off] : 0;
        __syncthreads();
        sh[t] += tv;
        __syncthreads();
    }
    if (t < nb) g_bsum[t] = sh[t] - v;                    // exclusive over block sums
    if (t == 0) g_rowptr[N_NODES] = N_EDGES;
}

// scan3 also re-zeros g_cnt (used as scatter cursor next)
__global__ void scan3_kernel() {
    int i = blockIdx.x * 1024 + threadIdx.x;
    if (i < N_NODES) {
        g_rowptr[i] += g_bsum[blockIdx.x];
        g_cnt[i] = 0;
    }
}

__global__ void scatter_kernel(const int* __restrict__ ei) {
    int e = blockIdx.x * blockDim.x + threadIdx.x;
    int sh = g_shift;
    if (e < N_EDGES) {
        int d = load_dst(ei, e, sh);
        int pos = g_rowptr[d] + atomicAdd(&g_cnt[d], 1);
        g_col[pos] = load_src(ei, e, sh);
    }
}

// ---------------- fused GEMM + attention-logit reduction ----------------
// h = X @ W  (K x 64) -> fp16 g_hh ; als = h . a_src, ald = h . a_dst (fp32 exact)
// NPB=32 nodes/block, 512 threads = 32 nodes x 16 threads; 4 output cols/thread.
#define NPB 32
template <int K, bool USE_GOUT>
__global__ void __launch_bounds__(NPB * 16) gemm_att_kernel(
    const float* __restrict__ X, const float* __restrict__ W,
    const float* __restrict__ avs, const float* __restrict__ avd)
{
    __shared__ __align__(16) float Ws[K * 64];
    __shared__ float Xs[NPB * K];
    __shared__ float As[64], Ad[64];

    int tid = threadIdx.x;
    for (int idx = tid; idx < K * 64; idx += NPB * 16) Ws[idx] = W[idx];
    if (tid < 64) { As[tid] = avs[tid]; Ad[tid] = avd[tid]; }
    int nb = blockIdx.x * NPB;
    const float* src_ptr = USE_GOUT ? g_out : X;
    {
        int lim = NPB * K;
        int base = nb * K;
        int maxe = N_NODES * K - base;
        for (int idx = tid; idx < lim; idx += NPB * 16)
            Xs[idx] = (idx < maxe) ? src_ptr[(size_t)base + idx] : 0.f;
    }
    __syncthreads();

    int nl = tid >> 4;
    int l16 = tid & 15;
    int node = nb + nl;
    float a0 = 0.f, a1 = 0.f, a2 = 0.f, a3 = 0.f;
    const float4* W4 = reinterpret_cast<const float4*>(Ws);
    const float* xr = &Xs[nl * K];
#pragma unroll
    for (int k = 0; k < K; k++) {
        float xv = xr[k];
        float4 w = W4[k * 16 + l16];
        a0 = fmaf(xv, w.x, a0);
        a1 = fmaf(xv, w.y, a1);
        a2 = fmaf(xv, w.z, a2);
        a3 = fmaf(xv, w.w, a3);
    }
    int c0 = l16 * 4;
    float ps = a0 * As[c0] + a1 * As[c0 + 1] + a2 * As[c0 + 2] + a3 * As[c0 + 3];
    float pd = a0 * Ad[c0] + a1 * Ad[c0 + 1] + a2 * Ad[c0 + 2] + a3 * Ad[c0 + 3];
#pragma unroll
    for (int off = 8; off; off >>= 1) {
        ps += __shfl_xor_sync(0xffffffffu, ps, off, 16);
        pd += __shfl_xor_sync(0xffffffffu, pd, off, 16);
    }
    if (node < N_NODES) {
        __half2 p0 = __floats2half2_rn(a0, a1);
        __half2 p1 = __floats2half2_rn(a2, a3);
        uint2 pk;
        pk.x = *reinterpret_cast<uint32_t*>(&p0);
        pk.y = *reinterpret_cast<uint32_t*>(&p1);
        *reinterpret_cast<uint2*>(&g_hh[(size_t)node * 32 + l16 * 2]) = pk;
        if (l16 == 0) { g_als[node] = ps; g_ald[node] = pd; }
    }
}

// ---------------- fused softmax aggregation (one warp per dst node) ----------------
// No max-subtraction: logits are O(+-25), expf is safe in fp32 and softmax is
// shift-invariant, so alpha is mathematically identical to the reference.
__global__ void __launch_bounds__(256) agg_kernel(const float* __restrict__ bias, int act) {
    int i = (blockIdx.x * blockDim.x + threadIdx.x) >> 5;
    int lane = threadIdx.x & 31;
    if (i >= N_NODES) return;

    const __half2* hrow = g_hh + lane;   // lane-fixed column offset (stride 32 half2/row)

    float ald_i = g_ald[i];
    // self-loop (PyG GATConv adds them)
    float e0 = g_als[i] + ald_i;
    e0 = (e0 >= 0.f) ? e0 : 0.2f * e0;
    float w0 = __expf(e0);
    float2 hv = __half22float2(hrow[(size_t)i * 32]);
    float a0 = w0 * hv.x, a1 = w0 * hv.y;
    float ssum = (lane == 0) ? w0 : 0.f;

    int beg = g_rowptr[i], end = g_rowptr[i + 1];
    for (int j0 = beg; j0 < end; j0 += 32) {
        int cnt = end - j0;
        if (cnt > 32) cnt = 32;
        int src = 0;
        float w = 0.f;
        if (lane < cnt) {
            src = g_col[j0 + lane];
            float e = g_als[src] + ald_i;
            e = (e >= 0.f) ? e : 0.2f * e;
            w = __expf(e);
        }
        ssum += w;

        // gather, 8-wide for MLP
        int jj = 0;
        for (; jj + 8 <= cnt; jj += 8) {
            float w0_ = __shfl_sync(0xffffffffu, w, jj);
            float w1_ = __shfl_sync(0xffffffffu, w, jj + 1);
            float w2_ = __shfl_sync(0xffffffffu, w, jj + 2);
            float w3_ = __shfl_sync(0xffffffffu, w, jj + 3);
            float w4_ = __shfl_sync(0xffffffffu, w, jj + 4);
            float w5_ = __shfl_sync(0xffffffffu, w, jj + 5);
            float w6_ = __shfl_sync(0xffffffffu, w, jj + 6);
            float w7_ = __shfl_sync(0xffffffffu, w, jj + 7);
            int s0 = __shfl_sync(0xffffffffu, src, jj);
            int s1 = __shfl_sync(0xffffffffu, src, jj + 1);
            int s2 = __shfl_sync(0xffffffffu, src, jj + 2);
            int s3 = __shfl_sync(0xffffffffu, src, jj + 3);
            int s4 = __shfl_sync(0xffffffffu, src, jj + 4);
            int s5 = __shfl_sync(0xffffffffu, src, jj + 5);
            int s6 = __shfl_sync(0xffffffffu, src, jj + 6);
            int s7 = __shfl_sync(0xffffffffu, src, jj + 7);
            float2 h0 = __half22float2(hrow[(size_t)s0 * 32]);
            float2 h1 = __half22float2(hrow[(size_t)s1 * 32]);
            float2 h2 = __half22float2(hrow[(size_t)s2 * 32]);
            float2 h3 = __half22float2(hrow[(size_t)s3 * 32]);
            float2 h4 = __half22float2(hrow[(size_t)s4 * 32]);
            float2 h5 = __half22float2(hrow[(size_t)s5 * 32]);
            float2 h6 = __half22float2(hrow[(size_t)s6 * 32]);
            float2 h7 = __half22float2(hrow[(size_t)s7 * 32]);
            a0 = fmaf(w0_, h0.x, a0); a1 = fmaf(w0_, h0.y, a1);
            a0 = fmaf(w1_, h1.x, a0); a1 = fmaf(w1_, h1.y, a1);
            a0 = fmaf(w2_, h2.x, a0); a1 = fmaf(w2_, h2.y, a1);
            a0 = fmaf(w3_, h3.x, a0); a1 = fmaf(w3_, h3.y, a1);
            a0 = fmaf(w4_, h4.x, a0); a1 = fmaf(w4_, h4.y, a1);
            a0 = fmaf(w5_, h5.x, a0); a1 = fmaf(w5_, h5.y, a1);
            a0 = fmaf(w6_, h6.x, a0); a1 = fmaf(w6_, h6.y, a1);
            a0 = fmaf(w7_, h7.x, a0); a1 = fmaf(w7_, h7.y, a1);
        }
        for (; jj < cnt; ++jj) {
            float wj = __shfl_sync(0xffffffffu, w, jj);
            int sj = __shfl_sync(0xffffffffu, src, jj);
            float2 hs = __half22float2(hrow[(size_t)sj * 32]);
            a0 = fmaf(wj, hs.x, a0);
            a1 = fmaf(wj, hs.y, a1);
        }
    }
    // one warp-sum at the end
#pragma unroll
    for (int off = 16; off; off >>= 1)
        ssum += __shfl_xor_sync(0xffffffffu, ssum, off);

    float inv = 1.f / (ssum + 1e-16f);
    float o0 = a0 * inv + bias[2 * lane];
    float o1 = a1 * inv + bias[2 * lane + 1];
    if (act) {
        o0 = (o0 >= 0.f) ? o0 : 0.01f * o0;
        o1 = (o1 >= 0.f) ? o1 : 0.01f * o1;
    }
    *reinterpret_cast<float2*>(&g_out[(size_t)i * 64 + 2 * lane]) = make_float2(o0, o1);
}

// ---------------- pooling (batch is sorted -> segment-flush accumulation) ----------------
#define POOL_CH 256
__global__ void __launch_bounds__(64) pool_kernel(const int* __restrict__ batch) {
    __shared__ int bsh[POOL_CH];
    int start = blockIdx.x * POOL_CH;
    int end = start + POOL_CH;
    if (end > N_NODES) end = N_NODES;
    int c = threadIdx.x;  // 0..63
    int sh = g_shift;
    for (int idx = c; idx < end - start; idx += 64)
        bsh[idx] = batch[(size_t)(start + idx) << sh];
    __syncthreads();
    if (start >= end) return;
    int cur = bsh[0];
    float acc = 0.f;
    int cnt = 0;
    for (int n = start; n < end; n++) {
        int b = bsh[n - start];
        if (b != cur) {
            atomicAdd(&g_pool[cur * 64 + c], acc);
            if (c == 0) atomicAdd(&g_pcnt[cur], cnt);
            acc = 0.f; cnt = 0; cur = b;
        }
        acc += g_out[(size_t)n * 64 + c];
        cnt++;
    }
    atomicAdd(&g_pool[cur * 64 + c], acc);
    if (c == 0) atomicAdd(&g_pcnt[cur], cnt);
}

// ---------------- final FC ----------------
__global__ void fc_kernel(const float* __restrict__ fcW, const float* __restrict__ fcb,
                          float* __restrict__ out) {
    int g = threadIdx.x;  // 256 graphs
    float cnt = fmaxf((float)g_pcnt[g], 1.f);
    float inv = 1.f / cnt;
    float o0 = fcb[0], o1 = fcb[1];
#pragma unroll
    for (int c = 0; c < 64; c++) {
        float p = g_pool[g * 64 + c] * inv;
        o0 = fmaf(p, fcW[2 * c], o0);
        o1 = fmaf(p, fcW[2 * c + 1], o1);
    }
    out[2 * g] = o0;
    out[2 * g + 1] = o1;
}

// ---------------- launch ----------------
extern "C" void kernel_launch(void* const* d_in, const int* in_sizes, int n_in,
                              void* d_out, int out_size) {
    const float* x      = (const float*)d_in[0];
    const int*   ei     = (const int*)d_in[1];    // int32 or int64 (detected on device)
    const int*   batch  = (const int*)d_in[2];
    const float* W1     = (const float*)d_in[3];
    const float* asrc1  = (const float*)d_in[4];
    const float* adst1  = (const float*)d_in[5];
    const float* b1     = (const float*)d_in[6];
    const float* W2     = (const float*)d_in[7];
    const float* asrc2  = (const float*)d_in[8];
    const float* adst2  = (const float*)d_in[9];
    const float* b2     = (const float*)d_in[10];
    const float* fcW    = (const float*)d_in[11];
    const float* fcb    = (const float*)d_in[12];
    float* out = (float*)d_out;

    // zero + dtype detect + CSR build (same graph used by both layers)
    zero_all_kernel<<<(N_NODES + 255) / 256, 256>>>(ei);
    count_kernel<<<(N_EDGES + 255) / 256, 256>>>(ei);
    scan1_kernel<<<SCAN_BLOCKS, 1024>>>();
    scan2_kernel<<<1, 128>>>(SCAN_BLOCKS);
    scan3_kernel<<<SCAN_BLOCKS, 1024>>>();
    scatter_kernel<<<(N_EDGES + 255) / 256, 256>>>(ei);

    // layer 1
    gemm_att_kernel<72, false><<<(N_NODES + NPB - 1) / NPB, NPB * 16>>>(x, W1, asrc1, adst1);
    agg_kernel<<<(N_NODES * 32 + 255) / 256, 256>>>(b1, 1);

    // layer 2 (input = g_out from layer 1, referenced directly in device code)
    gemm_att_kernel<64, true><<<(N_NODES + NPB - 1) / NPB, NPB * 16>>>(nullptr, W2, asrc2, adst2);
    agg_kernel<<<(N_NODES * 32 + 255) / 256, 256>>>(b2, 0);

    // pool + fc
    pool_kernel<<<(N_NODES + POOL_CH - 1) / POOL_CH, 64>>>(batch);
    fc_kernel<<<1, 256>>>(fcW, fcb, out);
}

// round 10
// speedup vs baseline: 1.3903x; 1.0502x over previous
#include <cuda_runtime.h>
#include <cuda_fp16.h>
#include <math.h>
#include <stdint.h>

#define N_NODES 100000
#define N_EDGES 1600000
#define N_GRAPHS 256
#define D_HID 64
#define SCAN_BLOCKS 98   // ceil(100000/1024); all co-resident on 148 SMs -> chain is safe

// ---------------- scratch (device globals; no allocation allowed) ----------------
__device__ __align__(16) __half2 g_hh[(size_t)N_NODES * 32];    // h rows in fp16 (64 cols = 32 half2)
__device__ __align__(16) float g_out[(size_t)N_NODES * D_HID];  // aggregated output per layer
__device__ float g_als[N_NODES];
__device__ float g_ald[N_NODES];
__device__ int   g_cnt[N_NODES];                  // histogram
__device__ int   g_rank[N_EDGES];                 // edge rank within its dst bucket
__device__ int   g_rowptr[N_NODES + 1];
__device__ int   g_col[N_EDGES];                  // src node per CSR slot
__device__ int   g_chain[SCAN_BLOCKS];            // scan prefix chain (-1 = not ready)
__device__ float g_pool[N_GRAPHS * D_HID];
__device__ int   g_pcnt[N_GRAPHS];
__device__ int   g_shift;                         // 0: indices are int32, 1: int64

__device__ __forceinline__ int load_src(const int* p, int e, int sh) {
    return p[(size_t)e << sh];
}
__device__ __forceinline__ int load_dst(const int* p, int e, int sh) {
    return p[((size_t)N_EDGES + e) << sh];
}

// ---------------- zero + index dtype detection (fused) ----------------
__global__ void zero_all_kernel(const int* __restrict__ ei32) {
    int i = blockIdx.x * blockDim.x + threadIdx.x;
    if (i < N_NODES) g_cnt[i] = 0;
    if (i < N_GRAPHS * D_HID) g_pool[i] = 0.f;
    if (i < N_GRAPHS) g_pcnt[i] = 0;
    if (i < SCAN_BLOCKS) g_chain[i] = -1;
    if (i == 0) {
        g_rowptr[N_NODES] = N_EDGES;
        int nz = 0;
#pragma unroll
        for (int k = 0; k < 16; k++) nz |= ei32[2 * k + 1];
        g_shift = (nz == 0) ? 1 : 0;
    }
}

// ---------------- CSR build ----------------
// count + per-edge rank in one pass (the atomic's return value is the rank)
__global__ void count_kernel(const int* __restrict__ ei) {
    int e = blockIdx.x * blockDim.x + threadIdx.x;
    int sh = g_shift;
    if (e < N_EDGES) g_rank[e] = atomicAdd(&g_cnt[load_dst(ei, e, sh)], 1);
}

// single-pass chained exclusive scan over g_cnt -> g_rowptr
__global__ void scan_kernel() {
    __shared__ int sh[1024];
    __shared__ int carry;
    int bx = blockIdx.x;
    int i = bx * 1024 + threadIdx.x;
    int v = (i < N_NODES) ? g_cnt[i] : 0;
    sh[threadIdx.x] = v;
    __syncthreads();
#pragma unroll
    for (int off = 1; off < 1024; off <<= 1) {
        int t = (threadIdx.x >= off) ? sh[threadIdx.x - off] : 0;
        __syncthreads();
        sh[threadIdx.x] += t;
        __syncthreads();
    }
    if (threadIdx.x == 0) {
        int c = 0;
        if (bx > 0) {
            volatile int* ch = g_chain;
            while ((c = ch[bx - 1]) < 0) {}
        }
        ((volatile int*)g_chain)[bx] = c + sh[1023];
        carry = c;
    }
    __syncthreads();
    if (i < N_NODES) g_rowptr[i] = carry + sh[threadIdx.x] - v;   // exclusive
}

// no atomics: slot = rowptr[dst] + rank[edge]
__global__ void scatter_kernel(const int* __restrict__ ei) {
    int e = blockIdx.x * blockDim.x + threadIdx.x;
    int sh = g_shift;
    if (e < N_EDGES) {
        int d = load_dst(ei, e, sh);
        g_col[g_rowptr[d] + g_rank[e]] = load_src(ei, e, sh);
    }
}

// ---------------- fused GEMM + attention-logit reduction ----------------
// h = X @ W  (K x 64) -> fp16 g_hh ; als = h . a_src, ald = h . a_dst (fp32 exact)
// NPB=32 nodes/block, 512 threads = 32 nodes x 16 threads; 4 output cols/thread.
#define NPB 32
template <int K, bool USE_GOUT>
__global__ void __launch_bounds__(NPB * 16) gemm_att_kernel(
    const float* __restrict__ X, const float* __restrict__ W,
    const float* __restrict__ avs, const float* __restrict__ avd)
{
    __shared__ __align__(16) float Ws[K * 64];
    __shared__ float Xs[NPB * K];
    __shared__ float As[64], Ad[64];

    int tid = threadIdx.x;
    for (int idx = tid; idx < K * 64; idx += NPB * 16) Ws[idx] = W[idx];
    if (tid < 64) { As[tid] = avs[tid]; Ad[tid] = avd[tid]; }
    int nb = blockIdx.x * NPB;
    const float* src_ptr = USE_GOUT ? g_out : X;
    {
        int lim = NPB * K;
        int base = nb * K;
        int maxe = N_NODES * K - base;
        for (int idx = tid; idx < lim; idx += NPB * 16)
            Xs[idx] = (idx < maxe) ? src_ptr[(size_t)base + idx] : 0.f;
    }
    __syncthreads();

    int nl = tid >> 4;
    int l16 = tid & 15;
    int node = nb + nl;
    float a0 = 0.f, a1 = 0.f, a2 = 0.f, a3 = 0.f;
    const float4* W4 = reinterpret_cast<const float4*>(Ws);
    const float* xr = &Xs[nl * K];
#pragma unroll
    for (int k = 0; k < K; k++) {
        float xv = xr[k];
        float4 w = W4[k * 16 + l16];
        a0 = fmaf(xv, w.x, a0);
        a1 = fmaf(xv, w.y, a1);
        a2 = fmaf(xv, w.z, a2);
        a3 = fmaf(xv, w.w, a3);
    }
    int c0 = l16 * 4;
    float ps = a0 * As[c0] + a1 * As[c0 + 1] + a2 * As[c0 + 2] + a3 * As[c0 + 3];
    float pd = a0 * Ad[c0] + a1 * Ad[c0 + 1] + a2 * Ad[c0 + 2] + a3 * Ad[c0 + 3];
#pragma unroll
    for (int off = 8; off; off >>= 1) {
        ps += __shfl_xor_sync(0xffffffffu, ps, off, 16);
        pd += __shfl_xor_sync(0xffffffffu, pd, off, 16);
    }
    if (node < N_NODES) {
        __half2 p0 = __floats2half2_rn(a0, a1);
        __half2 p1 = __floats2half2_rn(a2, a3);
        uint2 pk;
        pk.x = *reinterpret_cast<uint32_t*>(&p0);
        pk.y = *reinterpret_cast<uint32_t*>(&p1);
        *reinterpret_cast<uint2*>(&g_hh[(size_t)node * 32 + l16 * 2]) = pk;
        if (l16 == 0) { g_als[node] = ps; g_ald[node] = pd; }
    }
}

// ---------------- fused softmax aggregation (one warp per dst node) ----------------
// No max-subtraction: logits are O(+-25), expf is safe in fp32 and softmax is
// shift-invariant, so alpha is mathematically identical to the reference.
__global__ void __launch_bounds__(256) agg_kernel(const float* __restrict__ bias, int act) {
    int i = (blockIdx.x * blockDim.x + threadIdx.x) >> 5;
    int lane = threadIdx.x & 31;
    if (i >= N_NODES) return;

    const __half2* hrow = g_hh + lane;   // lane-fixed column offset (stride 32 half2/row)

    float ald_i = g_ald[i];
    // self-loop (PyG GATConv adds them)
    float e0 = g_als[i] + ald_i;
    e0 = (e0 >= 0.f) ? e0 : 0.2f * e0;
    float w0 = __expf(e0);
    float2 hv = __half22float2(hrow[(size_t)i * 32]);
    float a0 = w0 * hv.x, a1 = w0 * hv.y;   // even-edge accumulator pair
    float b0 = 0.f, b1 = 0.f;               // odd-edge accumulator pair
    float ssum = (lane == 0) ? w0 : 0.f;

    int beg = g_rowptr[i], end = g_rowptr[i + 1];
    for (int j0 = beg; j0 < end; j0 += 32) {
        int cnt = end - j0;
        if (cnt > 32) cnt = 32;
        int src = 0;
        float w = 0.f;
        if (lane < cnt) {
            src = g_col[j0 + lane];
            float e = g_als[src] + ald_i;
            e = (e >= 0.f) ? e : 0.2f * e;
            w = __expf(e);
        }
        ssum += w;

        // gather, 8-wide for MLP; two accumulator pairs break the FMA chain
        int jj = 0;
        for (; jj + 8 <= cnt; jj += 8) {
            float w0_ = __shfl_sync(0xffffffffu, w, jj);
            float w1_ = __shfl_sync(0xffffffffu, w, jj + 1);
            float w2_ = __shfl_sync(0xffffffffu, w, jj + 2);
            float w3_ = __shfl_sync(0xffffffffu, w, jj + 3);
            float w4_ = __shfl_sync(0xffffffffu, w, jj + 4);
            float w5_ = __shfl_sync(0xffffffffu, w, jj + 5);
            float w6_ = __shfl_sync(0xffffffffu, w, jj + 6);
            float w7_ = __shfl_sync(0xffffffffu, w, jj + 7);
            int s0 = __shfl_sync(0xffffffffu, src, jj);
            int s1 = __shfl_sync(0xffffffffu, src, jj + 1);
            int s2 = __shfl_sync(0xffffffffu, src, jj + 2);
            int s3 = __shfl_sync(0xffffffffu, src, jj + 3);
            int s4 = __shfl_sync(0xffffffffu, src, jj + 4);
            int s5 = __shfl_sync(0xffffffffu, src, jj + 5);
            int s6 = __shfl_sync(0xffffffffu, src, jj + 6);
            int s7 = __shfl_sync(0xffffffffu, src, jj + 7);
            float2 h0 = __half22float2(hrow[(size_t)s0 * 32]);
            float2 h1 = __half22float2(hrow[(size_t)s1 * 32]);
            float2 h2 = __half22float2(hrow[(size_t)s2 * 32]);
            float2 h3 = __half22float2(hrow[(size_t)s3 * 32]);
            float2 h4 = __half22float2(hrow[(size_t)s4 * 32]);
            float2 h5 = __half22float2(hrow[(size_t)s5 * 32]);
            float2 h6 = __half22float2(hrow[(size_t)s6 * 32]);
            float2 h7 = __half22float2(hrow[(size_t)s7 * 32]);
            a0 = fmaf(w0_, h0.x, a0); a1 = fmaf(w0_, h0.y, a1);
            b0 = fmaf(w1_, h1.x, b0); b1 = fmaf(w1_, h1.y, b1);
            a0 = fmaf(w2_, h2.x, a0); a1 = fmaf(w2_, h2.y, a1);
            b0 = fmaf(w3_, h3.x, b0); b1 = fmaf(w3_, h3.y, b1);
            a0 = fmaf(w4_, h4.x, a0); a1 = fmaf(w4_, h4.y, a1);
            b0 = fmaf(w5_, h5.x, b0); b1 = fmaf(w5_, h5.y, b1);
            a0 = fmaf(w6_, h6.x, a0); a1 = fmaf(w6_, h6.y, a1);
            b0 = fmaf(w7_, h7.x, b0); b1 = fmaf(w7_, h7.y, b1);
        }
        for (; jj < cnt; ++jj) {
            float wj = __shfl_sync(0xffffffffu, w, jj);
            int sj = __shfl_sync(0xffffffffu, src, jj);
            float2 hs = __half22float2(hrow[(size_t)sj * 32]);
            a0 = fmaf(wj, hs.x, a0);
            a1 = fmaf(wj, hs.y, a1);
        }
    }
    a0 += b0; a1 += b1;
    // one warp-sum at the end
#pragma unroll
    for (int off = 16; off; off >>= 1)
        ssum += __shfl_xor_sync(0xffffffffu, ssum, off);

    float inv = 1.f / (ssum + 1e-16f);
    float o0 = a0 * inv + bias[2 * lane];
    float o1 = a1 * inv + bias[2 * lane + 1];
    if (act) {
        o0 = (o0 >= 0.f) ? o0 : 0.01f * o0;
        o1 = (o1 >= 0.f) ? o1 : 0.01f * o1;
    }
    *reinterpret_cast<float2*>(&g_out[(size_t)i * 64 + 2 * lane]) = make_float2(o0, o1);
}

// ---------------- pooling (batch is sorted -> segment-flush accumulation) ----------------
// 256 threads = 4 sub-chunks x 64 columns; each thread serially scans 64 nodes.
#define POOL_CH 256
__global__ void __launch_bounds__(256) pool_kernel(const int* __restrict__ batch) {
    __shared__ int bsh[POOL_CH];
    int start = blockIdx.x * POOL_CH;
    int lim = N_NODES - start;
    if (lim > POOL_CH) lim = POOL_CH;
    int t = threadIdx.x;
    int sh = g_shift;
    if (t < lim) bsh[t] = batch[(size_t)(start + t) << sh];
    __syncthreads();
    int c = t & 63;
    int sub = t >> 6;          // 0..3
    int s0 = sub * 64;
    int s1 = s0 + 64;
    if (s1 > lim) s1 = lim;
    if (s0 >= s1) return;
    int cur = bsh[s0];
    float acc = 0.f;
    int cnt = 0;
    for (int n = s0; n < s1; n++) {
        int b = bsh[n];
        if (b != cur) {
            atomicAdd(&g_pool[cur * 64 + c], acc);
            if (c == 0) atomicAdd(&g_pcnt[cur], cnt);
            acc = 0.f; cnt = 0; cur = b;
        }
        acc += g_out[(size_t)(start + n) * 64 + c];
        cnt++;
    }
    atomicAdd(&g_pool[cur * 64 + c], acc);
    if (c == 0) atomicAdd(&g_pcnt[cur], cnt);
}

// ---------------- final FC ----------------
__global__ void fc_kernel(const float* __restrict__ fcW, const float* __restrict__ fcb,
                          float* __restrict__ out) {
    int g = threadIdx.x;  // 256 graphs
    float cnt = fmaxf((float)g_pcnt[g], 1.f);
    float inv = 1.f / cnt;
    float o0 = fcb[0], o1 = fcb[1];
#pragma unroll
    for (int c = 0; c < 64; c++) {
        float p = g_pool[g * 64 + c] * inv;
        o0 = fmaf(p, fcW[2 * c], o0);
        o1 = fmaf(p, fcW[2 * c + 1], o1);
    }
    out[2 * g] = o0;
    out[2 * g + 1] = o1;
}

// ---------------- launch ----------------
extern "C" void kernel_launch(void* const* d_in, const int* in_sizes, int n_in,
                              void* d_out, int out_size) {
    const float* x      = (const float*)d_in[0];
    const int*   ei     = (const int*)d_in[1];    // int32 or int64 (detected on device)
    const int*   batch  = (const int*)d_in[2];
    const float* W1     = (const float*)d_in[3];
    const float* asrc1  = (const float*)d_in[4];
    const float* adst1  = (const float*)d_in[5];
    const float* b1     = (const float*)d_in[6];
    const float* W2     = (const float*)d_in[7];
    const float* asrc2  = (const float*)d_in[8];
    const float* adst2  = (const float*)d_in[9];
    const float* b2     = (const float*)d_in[10];
    const float* fcW    = (const float*)d_in[11];
    const float* fcb    = (const float*)d_in[12];
    float* out = (float*)d_out;

    // zero + dtype detect + CSR build (same graph used by both layers)
    zero_all_kernel<<<(N_NODES + 255) / 256, 256>>>(ei);
    count_kernel<<<(N_EDGES + 255) / 256, 256>>>(ei);
    scan_kernel<<<SCAN_BLOCKS, 1024>>>();
    scatter_kernel<<<(N_EDGES + 255) / 256, 256>>>(ei);

    // layer 1
    gemm_att_kernel<72, false><<<(N_NODES + NPB - 1) / NPB, NPB * 16>>>(x, W1, asrc1, adst1);
    agg_kernel<<<(N_NODES * 32 + 255) / 256, 256>>>(b1, 1);

    // layer 2 (input = g_out from layer 1, referenced directly in device code)
    gemm_att_kernel<64, true><<<(N_NODES + NPB - 1) / NPB, NPB * 16>>>(nullptr, W2, asrc2, adst2);
    agg_kernel<<<(N_NODES * 32 + 255) / 256, 256>>>(b2, 0);

    // pool + fc
    pool_kernel<<<(N_NODES + POOL_CH - 1) / POOL_CH, 256>>>(batch);
    fc_kernel<<<1, 256>>>(fcW, fcb, out);
}

// round 13
// speedup vs baseline: 1.4189x; 1.0205x over previous
#include <cuda_runtime.h>
#include <cuda_fp16.h>
#include <math.h>
#include <stdint.h>

#define N_NODES 100000
#define N_EDGES 1600000
#define N_GRAPHS 256
#define D_HID 64
#define SCAN_BLOCKS 98   // ceil(100000/1024); all co-resident on 148 SMs -> chain is safe

// ---------------- scratch (device globals; no allocation allowed) ----------------
__device__ __align__(16) __half2 g_hh[(size_t)N_NODES * 32];    // h rows in fp16 (64 cols = 32 half2)
__device__ __align__(16) float g_out[(size_t)N_NODES * D_HID];  // aggregated output per layer
__device__ float g_als[N_NODES];
__device__ float g_ald[N_NODES];
__device__ int   g_cnt[N_NODES];                  // histogram
__device__ int   g_rank[N_EDGES];                 // edge rank within its dst bucket
__device__ int   g_dst[N_EDGES];                  // dst cached as int32 (coalesced for scatter)
__device__ int   g_rowptr[N_NODES + 1];
__device__ int   g_col[N_EDGES];                  // src node per CSR slot
__device__ int   g_chain[SCAN_BLOCKS];            // scan prefix chain (-1 = not ready)
__device__ float g_pool[N_GRAPHS * D_HID];
__device__ int   g_pcnt[N_GRAPHS];
__device__ int   g_shift;                         // 0: indices are int32, 1: int64

__device__ __forceinline__ int load_src(const int* p, int e, int sh) {
    return p[(size_t)e << sh];
}
__device__ __forceinline__ int load_dst(const int* p, int e, int sh) {
    return p[((size_t)N_EDGES + e) << sh];
}

// ---------------- zero + index dtype detection (fused) ----------------
__global__ void zero_all_kernel(const int* __restrict__ ei32) {
    int i = blockIdx.x * blockDim.x + threadIdx.x;
    if (i < N_NODES) g_cnt[i] = 0;
    if (i < N_GRAPHS * D_HID) g_pool[i] = 0.f;
    if (i < N_GRAPHS) g_pcnt[i] = 0;
    if (i < SCAN_BLOCKS) g_chain[i] = -1;
    if (i == 0) {
        g_rowptr[N_NODES] = N_EDGES;
        int nz = 0;
#pragma unroll
        for (int k = 0; k < 16; k++) nz |= ei32[2 * k + 1];
        g_shift = (nz == 0) ? 1 : 0;
    }
}

// ---------------- CSR build ----------------
// count + per-edge rank in one pass; cache dst as int32 for the scatter pass
__global__ void count_kernel(const int* __restrict__ ei) {
    int e = blockIdx.x * blockDim.x + threadIdx.x;
    int sh = g_shift;
    if (e < N_EDGES) {
        int d = load_dst(ei, e, sh);
        g_dst[e] = d;
        g_rank[e] = atomicAdd(&g_cnt[d], 1);
    }
}

// single-pass chained exclusive scan over g_cnt -> g_rowptr
__global__ void scan_kernel() {
    __shared__ int sh[1024];
    __shared__ int carry;
    int bx = blockIdx.x;
    int i = bx * 1024 + threadIdx.x;
    int v = (i < N_NODES) ? g_cnt[i] : 0;
    sh[threadIdx.x] = v;
    __syncthreads();
#pragma unroll
    for (int off = 1; off < 1024; off <<= 1) {
        int t = (threadIdx.x >= off) ? sh[threadIdx.x - off] : 0;
        __syncthreads();
        sh[threadIdx.x] += t;
        __syncthreads();
    }
    if (threadIdx.x == 0) {
        int c = 0;
        if (bx > 0) {
            volatile int* ch = g_chain;
            while ((c = ch[bx - 1]) < 0) {}
        }
        ((volatile int*)g_chain)[bx] = c + sh[1023];
        carry = c;
    }
    __syncthreads();
    if (i < N_NODES) g_rowptr[i] = carry + sh[threadIdx.x] - v;   // exclusive
}

// no atomics: slot = rowptr[dst] + rank[edge]
__global__ void scatter_kernel(const int* __restrict__ ei) {
    int e = blockIdx.x * blockDim.x + threadIdx.x;
    int sh = g_shift;
    if (e < N_EDGES) {
        int d = g_dst[e];
        g_col[g_rowptr[d] + g_rank[e]] = load_src(ei, e, sh);
    }
}

// ---------------- fused GEMM + attention-logit reduction ----------------
// h = X @ W  (K x 64) -> fp16 g_hh ; als = h . a_src, ald = h . a_dst (fp32 exact)
// NPB=32 nodes/block, 512 threads = 32 nodes x 16 threads; 4 output cols/thread.
#define NPB 32
template <int K, bool USE_GOUT>
__global__ void __launch_bounds__(NPB * 16) gemm_att_kernel(
    const float* __restrict__ X, const float* __restrict__ W,
    const float* __restrict__ avs, const float* __restrict__ avd)
{
    __shared__ __align__(16) float Ws[K * 64];
    __shared__ float Xs[NPB * K];
    __shared__ float As[64], Ad[64];

    int tid = threadIdx.x;
    for (int idx = tid; idx < K * 64; idx += NPB * 16) Ws[idx] = W[idx];
    if (tid < 64) { As[tid] = avs[tid]; Ad[tid] = avd[tid]; }
    int nb = blockIdx.x * NPB;
    const float* src_ptr = USE_GOUT ? g_out : X;
    {
        int lim = NPB * K;
        int base = nb * K;
        int maxe = N_NODES * K - base;
        for (int idx = tid; idx < lim; idx += NPB * 16)
            Xs[idx] = (idx < maxe) ? src_ptr[(size_t)base + idx] : 0.f;
    }
    __syncthreads();

    int nl = tid >> 4;
    int l16 = tid & 15;
    int node = nb + nl;
    float a0 = 0.f, a1 = 0.f, a2 = 0.f, a3 = 0.f;
    const float4* W4 = reinterpret_cast<const float4*>(Ws);
    const float* xr = &Xs[nl * K];
#pragma unroll
    for (int k = 0; k < K; k++) {
        float xv = xr[k];
        float4 w = W4[k * 16 + l16];
        a0 = fmaf(xv, w.x, a0);
        a1 = fmaf(xv, w.y, a1);
        a2 = fmaf(xv, w.z, a2);
        a3 = fmaf(xv, w.w, a3);
    }
    int c0 = l16 * 4;
    float ps = a0 * As[c0] + a1 * As[c0 + 1] + a2 * As[c0 + 2] + a3 * As[c0 + 3];
    float pd = a0 * Ad[c0] + a1 * Ad[c0 + 1] + a2 * Ad[c0 + 2] + a3 * Ad[c0 + 3];
#pragma unroll
    for (int off = 8; off; off >>= 1) {
        ps += __shfl_xor_sync(0xffffffffu, ps, off, 16);
        pd += __shfl_xor_sync(0xffffffffu, pd, off, 16);
    }
    if (node < N_NODES) {
        __half2 p0 = __floats2half2_rn(a0, a1);
        __half2 p1 = __floats2half2_rn(a2, a3);
        uint2 pk;
        pk.x = *reinterpret_cast<uint32_t*>(&p0);
        pk.y = *reinterpret_cast<uint32_t*>(&p1);
        *reinterpret_cast<uint2*>(&g_hh[(size_t)node * 32 + l16 * 2]) = pk;
        if (l16 == 0) { g_als[node] = ps; g_ald[node] = pd; }
    }
}

// ---------------- fused softmax aggregation ----------------
// One warp per dst node. Gather phase: 8 lanes per edge x 4 edges in flight.
// Each lane owns a 16B slice (8 fp16 cols) of the row -> LDG.128, 8 fp32 accs.
// No max-subtraction: logits are O(+-25), fp32 expf is safe; softmax shift-invariant.
__global__ void __launch_bounds__(256) agg_kernel(const float* __restrict__ bias, int act) {
    int i = (blockIdx.x * blockDim.x + threadIdx.x) >> 5;
    int lane = threadIdx.x & 31;
    if (i >= N_NODES) return;

    int grp = lane >> 3;          // 0..3  (edge slot)
    int slice = lane & 7;         // 0..7  (16B slice of the 128B row)
    const uint4* h4 = reinterpret_cast<const uint4*>(g_hh);

    float ald_i = g_ald[i];
    // self-loop (PyG GATConv adds them)
    float e0 = g_als[i] + ald_i;
    e0 = (e0 >= 0.f) ? e0 : 0.2f * e0;
    float w0 = __expf(e0);
    float ssum = (lane == 0) ? w0 : 0.f;

    float c0 = 0.f, c1 = 0.f, c2 = 0.f, c3 = 0.f, c4 = 0.f, c5 = 0.f, c6 = 0.f, c7 = 0.f;
    if (grp == 0) {  // group 0 contributes the self-loop once
        uint4 hv = h4[(size_t)i * 8 + slice];
        float2 f0 = __half22float2(*reinterpret_cast<__half2*>(&hv.x));
        float2 f1 = __half22float2(*reinterpret_cast<__half2*>(&hv.y));
        float2 f2 = __half22float2(*reinterpret_cast<__half2*>(&hv.z));
        float2 f3 = __half22float2(*reinterpret_cast<__half2*>(&hv.w));
        c0 = w0 * f0.x; c1 = w0 * f0.y; c2 = w0 * f1.x; c3 = w0 * f1.y;
        c4 = w0 * f2.x; c5 = w0 * f2.y; c6 = w0 * f3.x; c7 = w0 * f3.y;
    }

    int beg = g_rowptr[i], end = g_rowptr[i + 1];
    for (int j0 = beg; j0 < end; j0 += 32) {
        int cnt = end - j0;
        if (cnt > 32) cnt = 32;
        int src = 0;
        float w = 0.f;
        if (lane < cnt) {
            src = g_col[j0 + lane];
            float e = g_als[src] + ald_i;
            e = (e >= 0.f) ? e : 0.2f * e;
            w = __expf(e);
        }
        ssum += w;

        int iters = (cnt + 3) >> 2;       // warp-uniform
#pragma unroll 2
        for (int it = 0; it < iters; ++it) {
            int jj = it * 4 + grp;        // this group's edge within the chunk
            float wj = __shfl_sync(0xffffffffu, w, jj);
            int sj = __shfl_sync(0xffffffffu, src, jj);
            if (jj < cnt) {
                uint4 hv = h4[(size_t)sj * 8 + slice];
                float2 f0 = __half22float2(*reinterpret_cast<__half2*>(&hv.x));
                float2 f1 = __half22float2(*reinterpret_cast<__half2*>(&hv.y));
                float2 f2 = __half22float2(*reinterpret_cast<__half2*>(&hv.z));
                float2 f3 = __half22float2(*reinterpret_cast<__half2*>(&hv.w));
                c0 = fmaf(wj, f0.x, c0); c1 = fmaf(wj, f0.y, c1);
                c2 = fmaf(wj, f1.x, c2); c3 = fmaf(wj, f1.y, c3);
                c4 = fmaf(wj, f2.x, c4); c5 = fmaf(wj, f2.y, c5);
                c6 = fmaf(wj, f3.x, c6); c7 = fmaf(wj, f3.y, c7);
            }
        }
    }

    // cross-group reduction (lanes {l, l^8, l^16, l^24} hold the same columns)
#pragma unroll
    for (int off = 8; off <= 16; off <<= 1) {
        c0 += __shfl_xor_sync(0xffffffffu, c0, off);
        c1 += __shfl_xor_sync(0xffffffffu, c1, off);
        c2 += __shfl_xor_sync(0xffffffffu, c2, off);
        c3 += __shfl_xor_sync(0xffffffffu, c3, off);
        c4 += __shfl_xor_sync(0xffffffffu, c4, off);
        c5 += __shfl_xor_sync(0xffffffffu, c5, off);
        c6 += __shfl_xor_sync(0xffffffffu, c6, off);
        c7 += __shfl_xor_sync(0xffffffffu, c7, off);
    }
    // warp sum of weights
#pragma unroll
    for (int off = 16; off; off >>= 1)
        ssum += __shfl_xor_sync(0xffffffffu, ssum, off);

    if (grp == 0) {  // lanes 0..7 write 8 columns each
        float inv = 1.f / (ssum + 1e-16f);
        const float4* b4 = reinterpret_cast<const float4*>(bias);
        float4 bA = b4[slice * 2];
        float4 bB = b4[slice * 2 + 1];
        float o0 = c0 * inv + bA.x, o1 = c1 * inv + bA.y;
        float o2 = c2 * inv + bA.z, o3 = c3 * inv + bA.w;
        float o4 = c4 * inv + bB.x, o5 = c5 * inv + bB.y;
        float o6 = c6 * inv + bB.z, o7 = c7 * inv + bB.w;
        if (act) {
            o0 = (o0 >= 0.f) ? o0 : 0.01f * o0;
            o1 = (o1 >= 0.f) ? o1 : 0.01f * o1;
            o2 = (o2 >= 0.f) ? o2 : 0.01f * o2;
            o3 = (o3 >= 0.f) ? o3 : 0.01f * o3;
            o4 = (o4 >= 0.f) ? o4 : 0.01f * o4;
            o5 = (o5 >= 0.f) ? o5 : 0.01f * o5;
            o6 = (o6 >= 0.f) ? o6 : 0.01f * o6;
            o7 = (o7 >= 0.f) ? o7 : 0.01f * o7;
        }
        float4* orow = reinterpret_cast<float4*>(&g_out[(size_t)i * 64 + slice * 8]);
        orow[0] = make_float4(o0, o1, o2, o3);
        orow[1] = make_float4(o4, o5, o6, o7);
    }
}

// ---------------- pooling (batch is sorted -> segment-flush accumulation) ----------------
// 256 threads = 4 sub-chunks x 64 columns; each thread serially scans 64 nodes.
#define POOL_CH 256
__global__ void __launch_bounds__(256) pool_kernel(const int* __restrict__ batch) {
    __shared__ int bsh[POOL_CH];
    int start = blockIdx.x * POOL_CH;
    int lim = N_NODES - start;
    if (lim > POOL_CH) lim = POOL_CH;
    int t = threadIdx.x;
    int sh = g_shift;
    if (t < lim) bsh[t] = batch[(size_t)(start + t) << sh];
    __syncthreads();
    int c = t & 63;
    int sub = t >> 6;          // 0..3
    int s0 = sub * 64;
    int s1 = s0 + 64;
    if (s1 > lim) s1 = lim;
    if (s0 >= s1) return;
    int cur = bsh[s0];
    float acc = 0.f;
    int cnt = 0;
    for (int n = s0; n < s1; n++) {
        int b = bsh[n];
        if (b != cur) {
            atomicAdd(&g_pool[cur * 64 + c], acc);
            if (c == 0) atomicAdd(&g_pcnt[cur], cnt);
            acc = 0.f; cnt = 0; cur = b;
        }
        acc += g_out[(size_t)(start + n) * 64 + c];
        cnt++;
    }
    atomicAdd(&g_pool[cur * 64 + c], acc);
    if (c == 0) atomicAdd(&g_pcnt[cur], cnt);
}

// ---------------- final FC ----------------
__global__ void fc_kernel(const float* __restrict__ fcW, const float* __restrict__ fcb,
                          float* __restrict__ out) {
    int g = threadIdx.x;  // 256 graphs
    float cnt = fmaxf((float)g_pcnt[g], 1.f);
    float inv = 1.f / cnt;
    float o0 = fcb[0], o1 = fcb[1];
#pragma unroll
    for (int c = 0; c < 64; c++) {
        float p = g_pool[g * 64 + c] * inv;
        o0 = fmaf(p, fcW[2 * c], o0);
        o1 = fmaf(p, fcW[2 * c + 1], o1);
    }
    out[2 * g] = o0;
    out[2 * g + 1] = o1;
}

// ---------------- launch ----------------
extern "C" void kernel_launch(void* const* d_in, const int* in_sizes, int n_in,
                              void* d_out, int out_size) {
    const float* x      = (const float*)d_in[0];
    const int*   ei     = (const int*)d_in[1];    // int32 or int64 (detected on device)
    const int*   batch  = (const int*)d_in[2];
    const float* W1     = (const float*)d_in[3];
    const float* asrc1  = (const float*)d_in[4];
    const float* adst1  = (const float*)d_in[5];
    const float* b1     = (const float*)d_in[6];
    const float* W2     = (const float*)d_in[7];
    const float* asrc2  = (const float*)d_in[8];
    const float* adst2  = (const float*)d_in[9];
    const float* b2     = (const float*)d_in[10];
    const float* fcW    = (const float*)d_in[11];
    const float* fcb    = (const float*)d_in[12];
    float* out = (float*)d_out;

    // zero + dtype detect + CSR build (same graph used by both layers)
    zero_all_kernel<<<(N_NODES + 255) / 256, 256>>>(ei);
    count_kernel<<<(N_EDGES + 255) / 256, 256>>>(ei);
    scan_kernel<<<SCAN_BLOCKS, 1024>>>();
    scatter_kernel<<<(N_EDGES + 255) / 256, 256>>>(ei);

    // layer 1
    gemm_att_kernel<72, false><<<(N_NODES + NPB - 1) / NPB, NPB * 16>>>(x, W1, asrc1, adst1);
    agg_kernel<<<(N_NODES * 32 + 255) / 256, 256>>>(b1, 1);

    // layer 2 (input = g_out from layer 1, referenced directly in device code)
    gemm_att_kernel<64, true><<<(N_NODES + NPB - 1) / NPB, NPB * 16>>>(nullptr, W2, asrc2, adst2);
    agg_kernel<<<(N_NODES * 32 + 255) / 256, 256>>>(b2, 0);

    // pool + fc
    pool_kernel<<<(N_NODES + POOL_CH - 1) / POOL_CH, 256>>>(batch);
    fc_kernel<<<1, 256>>>(fcW, fcb, out);
}

// round 16
// speedup vs baseline: 1.8110x; 1.2763x over previous
#include <cuda_runtime.h>
#include <cuda_fp16.h>
#include <math.h>
#include <stdint.h>

#define N_NODES 100000
#define N_EDGES 1600000
#define N_GRAPHS 256
#define D_HID 64
#define SCAN_BLOCKS 25   // ceil(100000/4096); 25 co-resident blocks -> chain is safe

// ---------------- scratch (device globals; no allocation allowed) ----------------
__device__ __align__(16) __half2 g_hh[(size_t)N_NODES * 32];    // h rows in fp16 (64 cols = 32 half2)
__device__ __align__(16) float g_out[(size_t)N_NODES * D_HID];  // aggregated output per layer
__device__ float g_als[N_NODES];
__device__ float g_ald[N_NODES];
__device__ __align__(16) int g_cnt[N_NODES + 32]; // histogram (padded for int4 loads)
__device__ int   g_rank[N_EDGES];                 // edge rank within its dst bucket
__device__ int   g_dst[N_EDGES];                  // dst cached as int32 (coalesced for scatter)
__device__ int   g_rowptr[N_NODES + 1];
__device__ int   g_col[N_EDGES];                  // src node per CSR slot
__device__ int   g_chain[SCAN_BLOCKS];            // scan prefix chain (-1 = not ready)
__device__ float g_pool[N_GRAPHS * D_HID];
__device__ int   g_pcnt[N_GRAPHS];
__device__ int   g_shift;                         // 0: indices are int32, 1: int64

__device__ __forceinline__ int load_src(const int* p, int e, int sh) {
    return p[(size_t)e << sh];
}
__device__ __forceinline__ int load_dst(const int* p, int e, int sh) {
    return p[((size_t)N_EDGES + e) << sh];
}

// ---------------- zero + index dtype detection (fused) ----------------
__global__ void zero_all_kernel(const int* __restrict__ ei32) {
    int i = blockIdx.x * blockDim.x + threadIdx.x;
    if (i < N_NODES + 32) g_cnt[i] = 0;
    if (i < N_GRAPHS * D_HID) g_pool[i] = 0.f;
    if (i < N_GRAPHS) g_pcnt[i] = 0;
    if (i < SCAN_BLOCKS) g_chain[i] = -1;
    if (i == 0) {
        g_rowptr[N_NODES] = N_EDGES;
        int nz = 0;
#pragma unroll
        for (int k = 0; k < 16; k++) nz |= ei32[2 * k + 1];
        g_shift = (nz == 0) ? 1 : 0;
    }
}

// ---------------- CSR build ----------------
// count + per-edge rank in one pass; cache dst as int32 for the scatter pass
__global__ void count_kernel(const int* __restrict__ ei) {
    int e = blockIdx.x * blockDim.x + threadIdx.x;
    int sh = g_shift;
    if (e < N_EDGES) {
        int d = load_dst(ei, e, sh);
        g_dst[e] = d;
        g_rank[e] = atomicAdd(&g_cnt[d], 1);
    }
}

// single-pass chained exclusive scan over g_cnt -> g_rowptr (4 elems/thread)
__global__ void scan_kernel() {
    __shared__ int sh[1024];
    __shared__ int carry;
    int bx = blockIdx.x;
    int tid = threadIdx.x;
    int i0 = bx * 4096 + tid * 4;
    int4 v4 = *reinterpret_cast<const int4*>(&g_cnt[i0]);   // padded; OOB region is zeros
    if (i0 >= N_NODES) { v4.x = v4.y = v4.z = v4.w = 0; }
    else {
        if (i0 + 1 >= N_NODES) v4.y = 0;
        if (i0 + 2 >= N_NODES) v4.z = 0;
        if (i0 + 3 >= N_NODES) v4.w = 0;
    }
    int p0 = 0, p1 = v4.x, p2 = v4.x + v4.y, p3 = v4.x + v4.y + v4.z;
    int tsum = p3 + v4.w;
    sh[tid] = tsum;
    __syncthreads();
#pragma unroll
    for (int off = 1; off < 1024; off <<= 1) {
        int t = (tid >= off) ? sh[tid - off] : 0;
        __syncthreads();
        sh[tid] += t;
        __syncthreads();
    }
    if (tid == 0) {
        int c = 0;
        if (bx > 0) {
            volatile int* ch = g_chain;
            while ((c = ch[bx - 1]) < 0) {}
        }
        ((volatile int*)g_chain)[bx] = c + sh[1023];
        carry = c;
    }
    __syncthreads();
    int base = carry + sh[tid] - tsum;                      // exclusive prefix of this thread
    if (i0 < N_NODES)     g_rowptr[i0]     = base + p0;
    if (i0 + 1 < N_NODES) g_rowptr[i0 + 1] = base + p1;
    if (i0 + 2 < N_NODES) g_rowptr[i0 + 2] = base + p2;
    if (i0 + 3 < N_NODES) g_rowptr[i0 + 3] = base + p3;
}

// no atomics: slot = rowptr[dst] + rank[edge]
__global__ void scatter_kernel(const int* __restrict__ ei) {
    int e = blockIdx.x * blockDim.x + threadIdx.x;
    int sh = g_shift;
    if (e < N_EDGES) {
        int d = g_dst[e];
        g_col[g_rowptr[d] + g_rank[e]] = load_src(ei, e, sh);
    }
}

// ---------------- fused GEMM + attention-logit reduction ----------------
// h = X @ W  (K x 64) -> fp16 g_hh ; als = h . a_src, ald = h . a_dst (fp32 exact)
// 256 threads/block; each thread computes 4 nodes x 4 cols (register blocking).
// Block covers 64 nodes. Per k-step: 1 LDS.128 + 4 broadcast LDS.32 -> 16 FMA.
#define GNPB 64
template <int K, bool USE_GOUT>
__global__ void __launch_bounds__(256) gemm_att_kernel(
    const float* __restrict__ X, const float* __restrict__ W,
    const float* __restrict__ avs, const float* __restrict__ avd)
{
    __shared__ __align__(16) float Ws[K * 64];
    __shared__ float Xs[GNPB * K];
    __shared__ float As[64], Ad[64];

    int tid = threadIdx.x;
    for (int idx = tid; idx < K * 64; idx += 256) Ws[idx] = W[idx];
    if (tid < 64) { As[tid] = avs[tid]; Ad[tid] = avd[tid]; }
    int nb = blockIdx.x * GNPB;
    const float* src_ptr = USE_GOUT ? g_out : X;
    {
        int lim = GNPB * K;
        int base = nb * K;
        int maxe = N_NODES * K - base;
        for (int idx = tid; idx < lim; idx += 256)
            Xs[idx] = (idx < maxe) ? src_ptr[(size_t)base + idx] : 0.f;
    }
    __syncthreads();

    int l16 = tid & 15;     // col group: cols l16*4 .. +3
    int ng = tid >> 4;      // node group: nodes nb + ng*4 .. +3

    float acc[4][4];
#pragma unroll
    for (int n = 0; n < 4; n++)
#pragma unroll
        for (int c = 0; c < 4; c++) acc[n][c] = 0.f;

    const float4* W4 = reinterpret_cast<const float4*>(Ws);
    const float* x0 = &Xs[(ng * 4 + 0) * K];
    const float* x1 = &Xs[(ng * 4 + 1) * K];
    const float* x2 = &Xs[(ng * 4 + 2) * K];
    const float* x3 = &Xs[(ng * 4 + 3) * K];
#pragma unroll 8
    for (int k = 0; k < K; k++) {
        float4 w = W4[k * 16 + l16];
        float xv0 = x0[k], xv1 = x1[k], xv2 = x2[k], xv3 = x3[k];
        acc[0][0] = fmaf(xv0, w.x, acc[0][0]);
        acc[0][1] = fmaf(xv0, w.y, acc[0][1]);
        acc[0][2] = fmaf(xv0, w.z, acc[0][2]);
        acc[0][3] = fmaf(xv0, w.w, acc[0][3]);
        acc[1][0] = fmaf(xv1, w.x, acc[1][0]);
        acc[1][1] = fmaf(xv1, w.y, acc[1][1]);
        acc[1][2] = fmaf(xv1, w.z, acc[1][2]);
        acc[1][3] = fmaf(xv1, w.w, acc[1][3]);
        acc[2][0] = fmaf(xv2, w.x, acc[2][0]);
        acc[2][1] = fmaf(xv2, w.y, acc[2][1]);
        acc[2][2] = fmaf(xv2, w.z, acc[2][2]);
        acc[2][3] = fmaf(xv2, w.w, acc[2][3]);
        acc[3][0] = fmaf(xv3, w.x, acc[3][0]);
        acc[3][1] = fmaf(xv3, w.y, acc[3][1]);
        acc[3][2] = fmaf(xv3, w.z, acc[3][2]);
        acc[3][3] = fmaf(xv3, w.w, acc[3][3]);
    }

    int c0 = l16 * 4;
    float as0 = As[c0], as1 = As[c0 + 1], as2 = As[c0 + 2], as3 = As[c0 + 3];
    float ad0 = Ad[c0], ad1 = Ad[c0 + 1], ad2 = Ad[c0 + 2], ad3 = Ad[c0 + 3];
#pragma unroll
    for (int n = 0; n < 4; n++) {
        int node = nb + ng * 4 + n;
        float ps = acc[n][0] * as0 + acc[n][1] * as1 + acc[n][2] * as2 + acc[n][3] * as3;
        float pd = acc[n][0] * ad0 + acc[n][1] * ad1 + acc[n][2] * ad2 + acc[n][3] * ad3;
#pragma unroll
        for (int off = 8; off; off >>= 1) {
            ps += __shfl_xor_sync(0xffffffffu, ps, off, 16);
            pd += __shfl_xor_sync(0xffffffffu, pd, off, 16);
        }
        if (node < N_NODES) {
            __half2 p0 = __floats2half2_rn(acc[n][0], acc[n][1]);
            __half2 p1 = __floats2half2_rn(acc[n][2], acc[n][3]);
            uint2 pk;
            pk.x = *reinterpret_cast<uint32_t*>(&p0);
            pk.y = *reinterpret_cast<uint32_t*>(&p1);
            *reinterpret_cast<uint2*>(&g_hh[(size_t)node * 32 + l16 * 2]) = pk;
            if (l16 == 0) { g_als[node] = ps; g_ald[node] = pd; }
        }
    }
}

// ---------------- fused softmax aggregation ----------------
// One warp per dst node. Gather phase: 8 lanes per edge x 4 edges in flight.
// Each lane owns a 16B slice (8 fp16 cols) of the row -> LDG.128, 8 fp32 accs.
// No max-subtraction: logits are O(+-25), fp32 expf is safe; softmax shift-invariant.
__global__ void __launch_bounds__(256) agg_kernel(const float* __restrict__ bias, int act) {
    int i = (blockIdx.x * blockDim.x + threadIdx.x) >> 5;
    int lane = threadIdx.x & 31;
    if (i >= N_NODES) return;

    int grp = lane >> 3;          // 0..3  (edge slot)
    int slice = lane & 7;         // 0..7  (16B slice of the 128B row)
    const uint4* h4 = reinterpret_cast<const uint4*>(g_hh);

    float ald_i = g_ald[i];
    // self-loop (PyG GATConv adds them)
    float e0 = g_als[i] + ald_i;
    e0 = (e0 >= 0.f) ? e0 : 0.2f * e0;
    float w0 = __expf(e0);
    float ssum = (lane == 0) ? w0 : 0.f;

    float c0 = 0.f, c1 = 0.f, c2 = 0.f, c3 = 0.f, c4 = 0.f, c5 = 0.f, c6 = 0.f, c7 = 0.f;
    if (grp == 0) {  // group 0 contributes the self-loop once
        uint4 hv = h4[(size_t)i * 8 + slice];
        float2 f0 = __half22float2(*reinterpret_cast<__half2*>(&hv.x));
        float2 f1 = __half22float2(*reinterpret_cast<__half2*>(&hv.y));
        float2 f2 = __half22float2(*reinterpret_cast<__half2*>(&hv.z));
        float2 f3 = __half22float2(*reinterpret_cast<__half2*>(&hv.w));
        c0 = w0 * f0.x; c1 = w0 * f0.y; c2 = w0 * f1.x; c3 = w0 * f1.y;
        c4 = w0 * f2.x; c5 = w0 * f2.y; c6 = w0 * f3.x; c7 = w0 * f3.y;
    }

    int beg = g_rowptr[i], end = g_rowptr[i + 1];
    for (int j0 = beg; j0 < end; j0 += 32) {
        int cnt = end - j0;
        if (cnt > 32) cnt = 32;
        int src = 0;
        float w = 0.f;
        if (lane < cnt) {
            src = g_col[j0 + lane];
            float e = g_als[src] + ald_i;
            e = (e >= 0.f) ? e : 0.2f * e;
            w = __expf(e);
        }
        ssum += w;

        int iters = (cnt + 3) >> 2;       // warp-uniform
#pragma unroll 2
        for (int it = 0; it < iters; ++it) {
            int jj = it * 4 + grp;        // this group's edge within the chunk
            float wj = __shfl_sync(0xffffffffu, w, jj);
            int sj = __shfl_sync(0xffffffffu, src, jj);
            if (jj < cnt) {
                uint4 hv = h4[(size_t)sj * 8 + slice];
                float2 f0 = __half22float2(*reinterpret_cast<__half2*>(&hv.x));
                float2 f1 = __half22float2(*reinterpret_cast<__half2*>(&hv.y));
                float2 f2 = __half22float2(*reinterpret_cast<__half2*>(&hv.z));
                float2 f3 = __half22float2(*reinterpret_cast<__half2*>(&hv.w));
                c0 = fmaf(wj, f0.x, c0); c1 = fmaf(wj, f0.y, c1);
                c2 = fmaf(wj, f1.x, c2); c3 = fmaf(wj, f1.y, c3);
                c4 = fmaf(wj, f2.x, c4); c5 = fmaf(wj, f2.y, c5);
                c6 = fmaf(wj, f3.x, c6); c7 = fmaf(wj, f3.y, c7);
            }
        }
    }

    // cross-group reduction (lanes {l, l^8, l^16, l^24} hold the same columns)
#pragma unroll
    for (int off = 8; off <= 16; off <<= 1) {
        c0 += __shfl_xor_sync(0xffffffffu, c0, off);
        c1 += __shfl_xor_sync(0xffffffffu, c1, off);
        c2 += __shfl_xor_sync(0xffffffffu, c2, off);
        c3 += __shfl_xor_sync(0xffffffffu, c3, off);
        c4 += __shfl_xor_sync(0xffffffffu, c4, off);
        c5 += __shfl_xor_sync(0xffffffffu, c5, off);
        c6 += __shfl_xor_sync(0xffffffffu, c6, off);
        c7 += __shfl_xor_sync(0xffffffffu, c7, off);
    }
    // warp sum of weights
#pragma unroll
    for (int off = 16; off; off >>= 1)
        ssum += __shfl_xor_sync(0xffffffffu, ssum, off);

    if (grp == 0) {  // lanes 0..7 write 8 columns each
        float inv = 1.f / (ssum + 1e-16f);
        const float4* b4 = reinterpret_cast<const float4*>(bias);
        float4 bA = b4[slice * 2];
        float4 bB = b4[slice * 2 + 1];
        float o0 = c0 * inv + bA.x, o1 = c1 * inv + bA.y;
        float o2 = c2 * inv + bA.z, o3 = c3 * inv + bA.w;
        float o4 = c4 * inv + bB.x, o5 = c5 * inv + bB.y;
        float o6 = c6 * inv + bB.z, o7 = c7 * inv + bB.w;
        if (act) {
            o0 = (o0 >= 0.f) ? o0 : 0.01f * o0;
            o1 = (o1 >= 0.f) ? o1 : 0.01f * o1;
            o2 = (o2 >= 0.f) ? o2 : 0.01f * o2;
            o3 = (o3 >= 0.f) ? o3 : 0.01f * o3;
            o4 = (o4 >= 0.f) ? o4 : 0.01f * o4;
            o5 = (o5 >= 0.f) ? o5 : 0.01f * o5;
            o6 = (o6 >= 0.f) ? o6 : 0.01f * o6;
            o7 = (o7 >= 0.f) ? o7 : 0.01f * o7;
        }
        float4* orow = reinterpret_cast<float4*>(&g_out[(size_t)i * 64 + slice * 8]);
        orow[0] = make_float4(o0, o1, o2, o3);
        orow[1] = make_float4(o4, o5, o6, o7);
    }
}

// ---------------- pooling (batch is sorted -> segment-flush accumulation) ----------------
// 256 threads = 4 sub-chunks x 64 columns; each thread serially scans 64 nodes.
#define POOL_CH 256
__global__ void __launch_bounds__(256) pool_kernel(const int* __restrict__ batch) {
    __shared__ int bsh[POOL_CH];
    int start = blockIdx.x * POOL_CH;
    int lim = N_NODES - start;
    if (lim > POOL_CH) lim = POOL_CH;
    int t = threadIdx.x;
    int sh = g_shift;
    if (t < lim) bsh[t] = batch[(size_t)(start + t) << sh];
    __syncthreads();
    int c = t & 63;
    int sub = t >> 6;          // 0..3
    int s0 = sub * 64;
    int s1 = s0 + 64;
    if (s1 > lim) s1 = lim;
    if (s0 >= s1) return;
    int cur = bsh[s0];
    float acc = 0.f;
    int cnt = 0;
    for (int n = s0; n < s1; n++) {
        int b = bsh[n];
        if (b != cur) {
            atomicAdd(&g_pool[cur * 64 + c], acc);
            if (c == 0) atomicAdd(&g_pcnt[cur], cnt);
            acc = 0.f; cnt = 0; cur = b;
        }
        acc += g_out[(size_t)(start + n) * 64 + c];
        cnt++;
    }
    atomicAdd(&g_pool[cur * 64 + c], acc);
    if (c == 0) atomicAdd(&g_pcnt[cur], cnt);
}

// ---------------- final FC ----------------
__global__ void fc_kernel(const float* __restrict__ fcW, const float* __restrict__ fcb,
                          float* __restrict__ out) {
    int g = threadIdx.x;  // 256 graphs
    float cnt = fmaxf((float)g_pcnt[g], 1.f);
    float inv = 1.f / cnt;
    float o0 = fcb[0], o1 = fcb[1];
#pragma unroll
    for (int c = 0; c < 64; c++) {
        float p = g_pool[g * 64 + c] * inv;
        o0 = fmaf(p, fcW[2 * c], o0);
        o1 = fmaf(p, fcW[2 * c + 1], o1);
    }
    out[2 * g] = o0;
    out[2 * g + 1] = o1;
}

// ---------------- launch ----------------
extern "C" void kernel_launch(void* const* d_in, const int* in_sizes, int n_in,
                              void* d_out, int out_size) {
    const float* x      = (const float*)d_in[0];
    const int*   ei     = (const int*)d_in[1];    // int32 or int64 (detected on device)
    const int*   batch  = (const int*)d_in[2];
    const float* W1     = (const float*)d_in[3];
    const float* asrc1  = (const float*)d_in[4];
    const float* adst1  = (const float*)d_in[5];
    const float* b1     = (const float*)d_in[6];
    const float* W2     = (const float*)d_in[7];
    const float* asrc2  = (const float*)d_in[8];
    const float* adst2  = (const float*)d_in[9];
    const float* b2     = (const float*)d_in[10];
    const float* fcW    = (const float*)d_in[11];
    const float* fcb    = (const float*)d_in[12];
    float* out = (float*)d_out;

    // zero + dtype detect + CSR build (same graph used by both layers)
    zero_all_kernel<<<(N_NODES + 255) / 256, 256>>>(ei);
    count_kernel<<<(N_EDGES + 255) / 256, 256>>>(ei);
    scan_kernel<<<SCAN_BLOCKS, 1024>>>();
    scatter_kernel<<<(N_EDGES + 255) / 256, 256>>>(ei);

    // layer 1
    gemm_att_kernel<72, false><<<(N_NODES + GNPB - 1) / GNPB, 256>>>(x, W1, asrc1, adst1);
    agg_kernel<<<(N_NODES * 32 + 255) / 256, 256>>>(b1, 1);

    // layer 2 (input = g_out from layer 1, referenced directly in device code)
    gemm_att_kernel<64, true><<<(N_NODES + GNPB - 1) / GNPB, 256>>>(nullptr, W2, asrc2, adst2);
    agg_kernel<<<(N_NODES * 32 + 255) / 256, 256>>>(b2, 0);

    // pool + fc
    pool_kernel<<<(N_NODES + POOL_CH - 1) / POOL_CH, 256>>>(batch);
    fc_kernel<<<1, 256>>>(fcW, fcb, out);
}